// round 14
// baseline (speedup 1.0000x reference)
#include <cuda_runtime.h>
#include <float.h>
#include <stdint.h>

#define Bb 2
#define Hh 16
#define Ss 2048
#define Dd 64
#define BM 128          // query rows per CTA (4 warps x 32 rows)
#define BN 64           // key tile
#define NTHREADS 128
#define NTILES (Ss / BN)   // 32

// ---- shared memory layout (32-bit word offsets) ----
// K frags: [kg(8)][lane(32)][12]  (8 u32 payload + 4 pad; conflict-free LDS.128)
// V frags: [kgpair(4)][lane(32)][20] (16 u32 payload + 4 pad; ditto)
// Staging: raw f32 copies of the K and V tiles, filled by cp.async.
#define KLST 12
#define VLST 20
#define KGSZ (32 * KLST)                 // 384 u32 per key-group
#define VPSZ (32 * VLST)                 // 640 u32 per key-pair-group
#define OFF_MASK 0                       // [2048] additive mask row (f32)
#define OFF_K    2048                    // 8*384  = 3072 u32
#define OFF_V    (OFF_K + 8 * KGSZ)      // 5120: 4*640 = 2560 u32
#define OFF_SK   (OFF_V + 4 * VPSZ)      // 7680: staging K, 4096 u32 (16B-aligned)
#define OFF_SV   (OFF_SK + 4096)         // 11776: staging V, 4096 u32
#define SMEM_WORDS (OFF_SV + 4096)       // 15872 u32 = 63488 B

// ---------------------------------------------------------------------------
// helpers
// ---------------------------------------------------------------------------
__device__ __forceinline__ uint32_t h2(float lo, float hi) {
    uint32_t r;
    asm("cvt.rn.f16x2.f32 %0, %1, %2;" : "=r"(r) : "f"(hi), "f"(lo));
    return r;
}

// D += A*B, m16n8k16 f16 inputs, f32 accumulate (PTX fragment layouts)
__device__ __forceinline__ void mma16(float* d, const uint32_t* a,
                                      uint32_t b0, uint32_t b1) {
    asm volatile(
        "mma.sync.aligned.m16n8k16.row.col.f32.f16.f16.f32 "
        "{%0,%1,%2,%3},{%4,%5,%6,%7},{%8,%9},{%0,%1,%2,%3};"
        : "+f"(d[0]), "+f"(d[1]), "+f"(d[2]), "+f"(d[3])
        : "r"(a[0]), "r"(a[1]), "r"(a[2]), "r"(a[3]), "r"(b0), "r"(b1));
}

__device__ __forceinline__ void cp16(uint32_t smem_byte_addr, const void* gptr) {
    asm volatile("cp.async.cg.shared.global [%0], [%1], 16;"
                 :: "r"(smem_byte_addr), "l"(gptr) : "memory");
}
#define CP_COMMIT() asm volatile("cp.async.commit_group;" ::: "memory")
#define CP_WAIT0()  asm volatile("cp.async.wait_group 0;" ::: "memory")

// ---------------------------------------------------------------------------
// Mask prepass: single-block kernel (detect dtype, then expand to additive).
// jax bool may arrive byte-bool or int32; byte case scanned as u32 words —
// a random 0/1 byte-bool buffer yields some word >1 a.s.
// ---------------------------------------------------------------------------
__device__ float g_maskadd[Bb * Ss];

__global__ void mask_prep_kernel(const void* __restrict__ mask) {
    __shared__ int bad;
    if (threadIdx.x == 0) bad = 0;
    __syncthreads();
    const unsigned int* mw = (const unsigned int*)mask;
    for (int idx = threadIdx.x; idx < (Bb * Ss) / 4; idx += blockDim.x)
        if (mw[idx] > 1u) bad = 1;
    __syncthreads();
    const int is32 = bad ? 0 : 1;
    for (int idx = threadIdx.x; idx < Bb * Ss; idx += blockDim.x) {
        int mval = is32 ? ((const int*)mask)[idx]
                        : (int)((const unsigned char*)mask)[idx];
        g_maskadd[idx] = mval ? 0.0f : -FLT_MAX;
    }
}

// ---------------------------------------------------------------------------
// Main attention kernel: fp16 m16n8k16, cp.async K/V staging (no register
// round-trip), 3 CTAs/SM target. P packs directly into MMA2's A-frag.
// ---------------------------------------------------------------------------
__global__ void __launch_bounds__(NTHREADS, 3)
attn_kernel(const float* __restrict__ q,
            const float* __restrict__ k,
            const float* __restrict__ v,
            const float* __restrict__ taus,
            const float* __restrict__ bias,
            float* __restrict__ out)
{
    extern __shared__ float s[];
    uint32_t* su = (uint32_t*)s;
    const uint32_t sbase = (uint32_t)__cvta_generic_to_shared(s);

    const int tid  = threadIdx.x;
    const int wid  = tid >> 5;
    const int lane = tid & 31;
    const int g    = lane >> 2;    // groupID
    const int tig  = lane & 3;     // threadID_in_group

    const int itile = blockIdx.x;
    const int h     = blockIdx.y;
    const int b     = blockIdx.z;

    const int   plane = (b * Hh + h) * Ss;
    const float tau   = taus[h];
    const int   rowb  = wid * 32;
    const int   qgA   = itile * BM + rowb + g;   // row-block A, g-half row
    const int   qgB   = qgA + 16;                // row-block B

    const float4* ksrc = (const float4*)(k + (size_t)plane * Dd);
    const float4* vsrc = (const float4*)(v + (size_t)plane * Dd);

    // ---- issue cp.async staging for tile 0 immediately ----
#pragma unroll
    for (int it = 0; it < 8; it++) {
        const int idx = tid + it * NTHREADS;
        cp16(sbase + (OFF_SK + idx * 4) * 4, ksrc + idx);
        cp16(sbase + (OFF_SV + idx * 4) * 4, vsrc + idx);
    }
    CP_COMMIT();

    // ---- stage mask row ----
    {
        const float* madd = g_maskadd + b * Ss;
        for (int x = tid; x < Ss; x += NTHREADS) s[OFF_MASK + x] = madd[x];
    }

    // ---- Q fragments (f16x2), loaded once from gmem ----
    uint32_t qfA[4][4], qfB[4][4];
    {
        const float* qa0 = q + (size_t)(plane + qgA) * Dd;
        const float* qa1 = qa0 + 8 * Dd;
        const float* qb0 = q + (size_t)(plane + qgB) * Dd;
        const float* qb1 = qb0 + 8 * Dd;
#pragma unroll
        for (int k0 = 0; k0 < 4; k0++) {
            const int f = 16 * k0 + 2 * tig;
            qfA[k0][0] = h2(qa0[f],     qa0[f + 1]);
            qfA[k0][1] = h2(qa1[f],     qa1[f + 1]);
            qfA[k0][2] = h2(qa0[f + 8], qa0[f + 9]);
            qfA[k0][3] = h2(qa1[f + 8], qa1[f + 9]);
            qfB[k0][0] = h2(qb0[f],     qb0[f + 1]);
            qfB[k0][1] = h2(qb1[f],     qb1[f + 1]);
            qfB[k0][2] = h2(qb0[f + 8], qb0[f + 9]);
            qfB[k0][3] = h2(qb1[f + 8], qb1[f + 9]);
        }
    }

    float oaccA[8][4], oaccB[8][4];
#pragma unroll
    for (int n0 = 0; n0 < 8; n0++)
#pragma unroll
        for (int x = 0; x < 4; x++) { oaccA[n0][x] = 0.f; oaccB[n0][x] = 0.f; }
    float lA0 = 0.f, lA1 = 0.f, lB0 = 0.f, lB1 = 0.f;

    const float* browA0 = bias + ((size_t)b * Ss + qgA) * Ss;
    const float* browA1 = browA0 + 8 * Ss;
    const float* browB0 = browA0 + 16 * Ss;
    const float* browB1 = browA0 + 24 * Ss;

    const float4* SK4 = (const float4*)&s[OFF_SK];
    const float4* SV4 = (const float4*)&s[OFF_SV];

    for (int t = 0; t < NTILES; t++) {
        CP_WAIT0();            // staging holds tile t
        __syncthreads();       // ...visible to all; frags from t-1 consumed

        // ---- scatter staging -> fragment-packed f16x2 layout ----
        // K[key][f]: kg=key>>3; lane=(key&7)*4+((f&7)>>1); slot=(f>>4)*2+((f>>3)&1)
#pragma unroll
        for (int it = 0; it < 8; it++) {
            const int idx = tid + it * NTHREADS;
            const int key = idx >> 4, f = (idx & 15) * 4;
            const int kg = key >> 3;
            const int lane0 = (key & 7) * 4 + ((f & 7) >> 1);
            const int slot  = (f >> 4) * 2 + ((f >> 3) & 1);
            const float4 kv = SK4[idx];
            uint32_t* kb = &su[OFF_K + kg * KGSZ + slot];
            kb[lane0 * KLST]       = h2(kv.x, kv.y);
            kb[(lane0 + 1) * KLST] = h2(kv.z, kv.w);
        }
        // V keypair (2kp,2kp+1) col cc: kgpair=kp>>3; lane=(cc&7)*4+(kp&3);
        // slot=(cc>>3)*2+((kp>>2)&1); f16x2 low = even key.
#pragma unroll
        for (int it = 0; it < 4; it++) {
            const int task = tid + it * NTHREADS;
            const int kp = task >> 4, c = (task & 15) * 4;
            const int kgp = kp >> 3, tv = kp & 3, hi = (kp >> 2) & 1;
            const float4 v0 = SV4[(2 * kp) * 16 + (c >> 2)];
            const float4 v1 = SV4[(2 * kp + 1) * 16 + (c >> 2)];
            uint32_t* vb = &su[OFF_V + kgp * VPSZ + (c >> 3) * 2 + hi];
            const int lane0 = (c & 7) * 4 + tv;
            vb[lane0 * VLST]        = h2(v0.x, v1.x);
            vb[(lane0 + 4) * VLST]  = h2(v0.y, v1.y);
            vb[(lane0 + 8) * VLST]  = h2(v0.z, v1.z);
            vb[(lane0 + 12) * VLST] = h2(v0.w, v1.w);
        }
        __syncthreads();       // frags ready; staging fully consumed

        // ---- kick off async staging of tile t+1 ----
        if (t + 1 < NTILES) {
            const int base = (t + 1) * BN * 16;   // float4 index
#pragma unroll
            for (int it = 0; it < 8; it++) {
                const int idx = tid + it * NTHREADS;
                cp16(sbase + (OFF_SK + idx * 4) * 4, ksrc + base + idx);
                cp16(sbase + (OFF_SV + idx * 4) * 4, vsrc + base + idx);
            }
            CP_COMMIT();
        }

        const int j0 = t * BN;

        // ---- stream over 4 key-pair-groups (16 keys each) ----
#pragma unroll
        for (int kgp = 0; kgp < 4; kgp++) {
            uint32_t aA[4], aB[4];

            // -- two 8-key halves: MMA1 + softmax; pack P into A-frag --
#pragma unroll
            for (int half = 0; half < 2; half++) {
                const int kg = 2 * kgp + half;

                // K fragments: 2x LDS.128, conflict-free
                uint32_t kfr[8];
                {
                    const uint4* kp4 =
                        (const uint4*)&su[OFF_K + kg * KGSZ + lane * KLST];
                    *(uint4*)&kfr[0] = kp4[0];
                    *(uint4*)&kfr[4] = kp4[1];
                }

                // MMA1: S(32x8) = Q(32x64) @ K_kg^T  (4 K-steps of 16)
                float saA[4] = {0.f, 0.f, 0.f, 0.f};
                float saB[4] = {0.f, 0.f, 0.f, 0.f};
#pragma unroll
                for (int k0 = 0; k0 < 4; k0++) {
                    mma16(saA, qfA[k0], kfr[2 * k0], kfr[2 * k0 + 1]);
                    mma16(saB, qfB[k0], kfr[2 * k0], kfr[2 * k0 + 1]);
                }

                // softmax: scale + mask + tau*bias + exp
                const int jgl = j0 + kg * 8 + tig * 2;
                float2 mk   = *(const float2*)&s[OFF_MASK + jgl];
                float2 biA0 = *(const float2*)&browA0[jgl];
                float2 biA1 = *(const float2*)&browA1[jgl];
                float2 biB0 = *(const float2*)&browB0[jgl];
                float2 biB1 = *(const float2*)&browB1[jgl];
                // masked: x*0.125+(-FLT_MAX) -> -FLT_MAX; __expf(-FLT_MAX)==0
                float pA0 = __expf(fmaf(saA[0], 0.125f, mk.x) - tau * biA0.x);
                float pA1 = __expf(fmaf(saA[1], 0.125f, mk.y) - tau * biA0.y);
                float pA2 = __expf(fmaf(saA[2], 0.125f, mk.x) - tau * biA1.x);
                float pA3 = __expf(fmaf(saA[3], 0.125f, mk.y) - tau * biA1.y);
                float pB0 = __expf(fmaf(saB[0], 0.125f, mk.x) - tau * biB0.x);
                float pB1 = __expf(fmaf(saB[1], 0.125f, mk.y) - tau * biB0.y);
                float pB2 = __expf(fmaf(saB[2], 0.125f, mk.x) - tau * biB1.x);
                float pB3 = __expf(fmaf(saB[3], 0.125f, mk.y) - tau * biB1.y);
                lA0 += pA0 + pA1;  lA1 += pA2 + pA3;
                lB0 += pB0 + pB1;  lB1 += pB2 + pB3;

                // D-frag -> A-frag (f16x2 pack), no shuffles
                aA[2 * half]     = h2(pA0, pA1);
                aA[2 * half + 1] = h2(pA2, pA3);
                aB[2 * half]     = h2(pB0, pB1);
                aB[2 * half + 1] = h2(pB2, pB3);
            }

            // V fragments: 4x LDS.128, conflict-free
            uint32_t vfr[16];
            {
                const uint4* vp4 =
                    (const uint4*)&su[OFF_V + kgp * VPSZ + lane * VLST];
                *(uint4*)&vfr[0]  = vp4[0];
                *(uint4*)&vfr[4]  = vp4[1];
                *(uint4*)&vfr[8]  = vp4[2];
                *(uint4*)&vfr[12] = vp4[3];
            }

            // MMA2: O(32x64) += P(32x16) @ V(16x64)
#pragma unroll
            for (int n0 = 0; n0 < 8; n0++) {
                mma16(oaccA[n0], aA, vfr[2 * n0], vfr[2 * n0 + 1]);
                mma16(oaccB[n0], aB, vfr[2 * n0], vfr[2 * n0 + 1]);
            }
        }
    }

    // ---- reduce l across the 4 lanes sharing each row ----
    lA0 += __shfl_xor_sync(0xffffffffu, lA0, 1);
    lA0 += __shfl_xor_sync(0xffffffffu, lA0, 2);
    lA1 += __shfl_xor_sync(0xffffffffu, lA1, 1);
    lA1 += __shfl_xor_sync(0xffffffffu, lA1, 2);
    lB0 += __shfl_xor_sync(0xffffffffu, lB0, 1);
    lB0 += __shfl_xor_sync(0xffffffffu, lB0, 2);
    lB1 += __shfl_xor_sync(0xffffffffu, lB1, 1);
    lB1 += __shfl_xor_sync(0xffffffffu, lB1, 2);
    const float invA0 = 1.0f / lA0;
    const float invA1 = 1.0f / lA1;
    const float invB0 = 1.0f / lB0;
    const float invB1 = 1.0f / lB1;

    // ---- normalize + write O ----
    float* oA0 = out + (size_t)(plane + qgA) * Dd;
    float* oA1 = oA0 + 8 * Dd;
    float* oB0 = out + (size_t)(plane + qgB) * Dd;
    float* oB1 = oB0 + 8 * Dd;
#pragma unroll
    for (int n0 = 0; n0 < 8; n0++) {
        *(float2*)&oA0[n0 * 8 + 2 * tig] =
            make_float2(oaccA[n0][0] * invA0, oaccA[n0][1] * invA0);
        *(float2*)&oA1[n0 * 8 + 2 * tig] =
            make_float2(oaccA[n0][2] * invA1, oaccA[n0][3] * invA1);
        *(float2*)&oB0[n0 * 8 + 2 * tig] =
            make_float2(oaccB[n0][0] * invB0, oaccB[n0][1] * invB0);
        *(float2*)&oB1[n0 * 8 + 2 * tig] =
            make_float2(oaccB[n0][2] * invB1, oaccB[n0][3] * invB1);
    }
}

// ---------------------------------------------------------------------------
extern "C" void kernel_launch(void* const* d_in, const int* in_sizes, int n_in,
                              void* d_out, int out_size) {
    const float* q    = (const float*)d_in[0];
    const float* k    = (const float*)d_in[1];
    const float* v    = (const float*)d_in[2];
    const void*  mask = d_in[3];
    const float* taus = (const float*)d_in[4];
    const float* bias = (const float*)d_in[5];
    float*       out  = (float*)d_out;
    (void)in_sizes; (void)n_in; (void)out_size;

    const int smem_bytes = SMEM_WORDS * 4;
    cudaFuncSetAttribute(attn_kernel, cudaFuncAttributeMaxDynamicSharedMemorySize,
                         smem_bytes);

    mask_prep_kernel<<<1, 1024>>>(mask);

    dim3 grid(Ss / BM, Hh, Bb);
    attn_kernel<<<grid, NTHREADS, smem_bytes>>>(q, k, v, taus, bias, out);
}

// round 15
// speedup vs baseline: 1.4071x; 1.4071x over previous
#include <cuda_runtime.h>
#include <float.h>
#include <stdint.h>

#define Bb 2
#define Hh 16
#define Ss 2048
#define Dd 64
#define BM 128          // query rows per CTA (4 warps x 32 rows)
#define BN 64           // key tile
#define NTHREADS 128
#define NTILES (Ss / BN)   // 32

// ---- shared memory layout (32-bit word offsets) ----
// K frags: [kg(8)][lane(32)][12]  (8 u32 payload + 4 pad; conflict-free LDS.128)
// V frags: [kgpair(4)][lane(32)][20] (16 u32 payload + 4 pad; ditto)
#define KLST 12
#define VLST 20
#define KGSZ (32 * KLST)                 // 384 u32 per key-group
#define VPSZ (32 * VLST)                 // 640 u32 per key-pair-group
#define OFF_MASK 0                       // [2048] additive mask row (f32)
#define OFF_K    2048                    // 8*384  = 3072 u32
#define OFF_V    (OFF_K + 8 * KGSZ)      // 5120: 4*640 = 2560 u32
#define SMEM_WORDS (OFF_V + 4 * VPSZ)    // 7680 u32 = 30720 B

// ---------------------------------------------------------------------------
// helpers
// ---------------------------------------------------------------------------
__device__ __forceinline__ uint32_t h2(float lo, float hi) {
    uint32_t r;
    asm("cvt.rn.f16x2.f32 %0, %1, %2;" : "=r"(r) : "f"(hi), "f"(lo));
    return r;
}

// D += A*B, m16n8k16 f16 inputs, f32 accumulate (PTX fragment layouts)
__device__ __forceinline__ void mma16(float* d, const uint32_t* a,
                                      uint32_t b0, uint32_t b1) {
    asm volatile(
        "mma.sync.aligned.m16n8k16.row.col.f32.f16.f16.f32 "
        "{%0,%1,%2,%3},{%4,%5,%6,%7},{%8,%9},{%0,%1,%2,%3};"
        : "+f"(d[0]), "+f"(d[1]), "+f"(d[2]), "+f"(d[3])
        : "r"(a[0]), "r"(a[1]), "r"(a[2]), "r"(a[3]), "r"(b0), "r"(b1));
}

// ---------------------------------------------------------------------------
// Mask prepass: single-block kernel (detect dtype, then expand to additive).
// jax bool may arrive byte-bool or int32; byte case scanned as u32 words —
// a random 0/1 byte-bool buffer yields some word >1 a.s.
// ---------------------------------------------------------------------------
__device__ float g_maskadd[Bb * Ss];

__global__ void mask_prep_kernel(const void* __restrict__ mask) {
    __shared__ int bad;
    if (threadIdx.x == 0) bad = 0;
    __syncthreads();
    const unsigned int* mw = (const unsigned int*)mask;
    for (int idx = threadIdx.x; idx < (Bb * Ss) / 4; idx += blockDim.x)
        if (mw[idx] > 1u) bad = 1;
    __syncthreads();
    const int is32 = bad ? 0 : 1;
    for (int idx = threadIdx.x; idx < Bb * Ss; idx += blockDim.x) {
        int mval = is32 ? ((const int*)mask)[idx]
                        : (int)((const unsigned char*)mask)[idx];
        g_maskadd[idx] = mval ? 0.0f : -FLT_MAX;
    }
}

// ---------------------------------------------------------------------------
// Main attention kernel: fp16 m16n8k16 pipeline, 32 rows/warp (A/B blocks).
// K prefetched through registers (tile t+1); V loaded by LDG at scatter time
// (latency covered by the K scatter + warp overlap) so only 32 prefetch regs
// stay live across the compute phase (R13 spilled at 255 regs with 64).
// ---------------------------------------------------------------------------
__global__ void __launch_bounds__(NTHREADS)
attn_kernel(const float* __restrict__ q,
            const float* __restrict__ k,
            const float* __restrict__ v,
            const float* __restrict__ taus,
            const float* __restrict__ bias,
            float* __restrict__ out)
{
    extern __shared__ float s[];
    uint32_t* su = (uint32_t*)s;

    const int tid  = threadIdx.x;
    const int wid  = tid >> 5;
    const int lane = tid & 31;
    const int g    = lane >> 2;    // groupID
    const int tig  = lane & 3;     // threadID_in_group

    const int itile = blockIdx.x;
    const int h     = blockIdx.y;
    const int b     = blockIdx.z;

    const int   plane = (b * Hh + h) * Ss;
    const float tau   = taus[h];
    const int   rowb  = wid * 32;
    const int   qgA   = itile * BM + rowb + g;   // row-block A, g-half row
    const int   qgB   = qgA + 16;                // row-block B

    // ---- stage mask row ----
    {
        const float* madd = g_maskadd + b * Ss;
        for (int x = tid; x < Ss; x += NTHREADS) s[OFF_MASK + x] = madd[x];
    }

    // ---- Q fragments (f16x2), loaded once from gmem ----
    uint32_t qfA[4][4], qfB[4][4];
    {
        const float* qa0 = q + (size_t)(plane + qgA) * Dd;
        const float* qa1 = qa0 + 8 * Dd;
        const float* qb0 = q + (size_t)(plane + qgB) * Dd;
        const float* qb1 = qb0 + 8 * Dd;
#pragma unroll
        for (int k0 = 0; k0 < 4; k0++) {
            const int f = 16 * k0 + 2 * tig;
            qfA[k0][0] = h2(qa0[f],     qa0[f + 1]);
            qfA[k0][1] = h2(qa1[f],     qa1[f + 1]);
            qfA[k0][2] = h2(qa0[f + 8], qa0[f + 9]);
            qfA[k0][3] = h2(qa1[f + 8], qa1[f + 9]);
            qfB[k0][0] = h2(qb0[f],     qb0[f + 1]);
            qfB[k0][1] = h2(qb1[f],     qb1[f + 1]);
            qfB[k0][2] = h2(qb0[f + 8], qb0[f + 9]);
            qfB[k0][3] = h2(qb1[f + 8], qb1[f + 9]);
        }
    }

    float oaccA[8][4], oaccB[8][4];
#pragma unroll
    for (int n0 = 0; n0 < 8; n0++)
#pragma unroll
        for (int x = 0; x < 4; x++) { oaccA[n0][x] = 0.f; oaccB[n0][x] = 0.f; }
    float lA0 = 0.f, lA1 = 0.f, lB0 = 0.f, lB1 = 0.f;

    const float4* ksrc = (const float4*)(k + (size_t)plane * Dd);
    const float4* vsrc = (const float4*)(v + (size_t)plane * Dd);
    const float* browA0 = bias + ((size_t)b * Ss + qgA) * Ss;
    const float* browA1 = browA0 + 8 * Ss;
    const float* browB0 = browA0 + 16 * Ss;
    const float* browB1 = browA0 + 24 * Ss;

    // ---- prefetch K tile 0 into registers ----
    float4 kbuf[8];
#pragma unroll
    for (int it = 0; it < 8; it++) kbuf[it] = ksrc[tid + it * NTHREADS];

    for (int t = 0; t < NTILES; t++) {
        const int base = t * BN * 16;   // float4 index of tile t

        // ---- issue V loads for tile t (covered by the K scatter below) ----
        float4 v0[4], v1[4];
#pragma unroll
        for (int it = 0; it < 4; it++) {
            const int task = tid + it * NTHREADS;
            const int kp = task >> 4, c4 = task & 15;
            v0[it] = vsrc[base + (2 * kp) * 16 + c4];
            v1[it] = vsrc[base + (2 * kp + 1) * 16 + c4];
        }

        // ---- scatter K (from kbuf regs) into fragment-packed f16x2 layout ----
        // K[key][f]: kg=key>>3; lane=(key&7)*4+((f&7)>>1); slot=(f>>4)*2+((f>>3)&1)
#pragma unroll
        for (int it = 0; it < 8; it++) {
            const int idx = tid + it * NTHREADS;
            const int key = idx >> 4, f = (idx & 15) * 4;
            const int kg = key >> 3;
            const int lane0 = (key & 7) * 4 + ((f & 7) >> 1);
            const int slot  = (f >> 4) * 2 + ((f >> 3) & 1);
            uint32_t* kb = &su[OFF_K + kg * KGSZ + slot];
            kb[lane0 * KLST]       = h2(kbuf[it].x, kbuf[it].y);
            kb[(lane0 + 1) * KLST] = h2(kbuf[it].z, kbuf[it].w);
        }

        // ---- scatter V (from just-loaded regs) ----
        // V keypair (2kp,2kp+1) col cc: kgpair=kp>>3; lane=(cc&7)*4+(kp&3);
        // slot=(cc>>3)*2+((kp>>2)&1); f16x2 low = even key.
#pragma unroll
        for (int it = 0; it < 4; it++) {
            const int task = tid + it * NTHREADS;
            const int kp = task >> 4, c = (task & 15) * 4;
            const int kgp = kp >> 3, tv = kp & 3, hi = (kp >> 2) & 1;
            uint32_t* vb = &su[OFF_V + kgp * VPSZ + (c >> 3) * 2 + hi];
            const int lane0 = (c & 7) * 4 + tv;
            vb[lane0 * VLST]        = h2(v0[it].x, v1[it].x);
            vb[(lane0 + 4) * VLST]  = h2(v0[it].y, v1[it].y);
            vb[(lane0 + 8) * VLST]  = h2(v0[it].z, v1[it].z);
            vb[(lane0 + 12) * VLST] = h2(v0[it].w, v1[it].w);
        }
        __syncthreads();

        // ---- prefetch NEXT K tile (latency hidden behind compute) ----
        if (t + 1 < NTILES) {
            const int nbase = (t + 1) * BN * 16;
#pragma unroll
            for (int it = 0; it < 8; it++)
                kbuf[it] = ksrc[nbase + tid + it * NTHREADS];
        }

        const int j0 = t * BN;

        // ---- stream over 4 key-pair-groups (16 keys each) ----
#pragma unroll
        for (int kgp = 0; kgp < 4; kgp++) {
            uint32_t aA[4], aB[4];

            // -- two 8-key halves: MMA1 + softmax; pack P into A-frag --
#pragma unroll
            for (int half = 0; half < 2; half++) {
                const int kg = 2 * kgp + half;

                // K fragments: 2x LDS.128, conflict-free
                uint32_t kfr[8];
                {
                    const uint4* kp4 =
                        (const uint4*)&su[OFF_K + kg * KGSZ + lane * KLST];
                    *(uint4*)&kfr[0] = kp4[0];
                    *(uint4*)&kfr[4] = kp4[1];
                }

                // MMA1: S(32x8) = Q(32x64) @ K_kg^T  (4 K-steps of 16)
                float saA[4] = {0.f, 0.f, 0.f, 0.f};
                float saB[4] = {0.f, 0.f, 0.f, 0.f};
#pragma unroll
                for (int k0 = 0; k0 < 4; k0++) {
                    mma16(saA, qfA[k0], kfr[2 * k0], kfr[2 * k0 + 1]);
                    mma16(saB, qfB[k0], kfr[2 * k0], kfr[2 * k0 + 1]);
                }

                // softmax: scale + mask + tau*bias + exp
                const int jgl = j0 + kg * 8 + tig * 2;
                float2 mk   = *(const float2*)&s[OFF_MASK + jgl];
                float2 biA0 = *(const float2*)&browA0[jgl];
                float2 biA1 = *(const float2*)&browA1[jgl];
                float2 biB0 = *(const float2*)&browB0[jgl];
                float2 biB1 = *(const float2*)&browB1[jgl];
                // masked: x*0.125+(-FLT_MAX) -> -FLT_MAX; __expf(-FLT_MAX)==0
                float pA0 = __expf(fmaf(saA[0], 0.125f, mk.x) - tau * biA0.x);
                float pA1 = __expf(fmaf(saA[1], 0.125f, mk.y) - tau * biA0.y);
                float pA2 = __expf(fmaf(saA[2], 0.125f, mk.x) - tau * biA1.x);
                float pA3 = __expf(fmaf(saA[3], 0.125f, mk.y) - tau * biA1.y);
                float pB0 = __expf(fmaf(saB[0], 0.125f, mk.x) - tau * biB0.x);
                float pB1 = __expf(fmaf(saB[1], 0.125f, mk.y) - tau * biB0.y);
                float pB2 = __expf(fmaf(saB[2], 0.125f, mk.x) - tau * biB1.x);
                float pB3 = __expf(fmaf(saB[3], 0.125f, mk.y) - tau * biB1.y);
                lA0 += pA0 + pA1;  lA1 += pA2 + pA3;
                lB0 += pB0 + pB1;  lB1 += pB2 + pB3;

                // D-frag -> A-frag (f16x2 pack), no shuffles
                aA[2 * half]     = h2(pA0, pA1);
                aA[2 * half + 1] = h2(pA2, pA3);
                aB[2 * half]     = h2(pB0, pB1);
                aB[2 * half + 1] = h2(pB2, pB3);
            }

            // V fragments: 4x LDS.128, conflict-free
            uint32_t vfr[16];
            {
                const uint4* vp4 =
                    (const uint4*)&su[OFF_V + kgp * VPSZ + lane * VLST];
                *(uint4*)&vfr[0]  = vp4[0];
                *(uint4*)&vfr[4]  = vp4[1];
                *(uint4*)&vfr[8]  = vp4[2];
                *(uint4*)&vfr[12] = vp4[3];
            }

            // MMA2: O(32x64) += P(32x16) @ V(16x64)
#pragma unroll
            for (int n0 = 0; n0 < 8; n0++) {
                mma16(oaccA[n0], aA, vfr[2 * n0], vfr[2 * n0 + 1]);
                mma16(oaccB[n0], aB, vfr[2 * n0], vfr[2 * n0 + 1]);
            }
        }
        __syncthreads();   // all warps done with K/V frags before restage
    }

    // ---- reduce l across the 4 lanes sharing each row ----
    lA0 += __shfl_xor_sync(0xffffffffu, lA0, 1);
    lA0 += __shfl_xor_sync(0xffffffffu, lA0, 2);
    lA1 += __shfl_xor_sync(0xffffffffu, lA1, 1);
    lA1 += __shfl_xor_sync(0xffffffffu, lA1, 2);
    lB0 += __shfl_xor_sync(0xffffffffu, lB0, 1);
    lB0 += __shfl_xor_sync(0xffffffffu, lB0, 2);
    lB1 += __shfl_xor_sync(0xffffffffu, lB1, 1);
    lB1 += __shfl_xor_sync(0xffffffffu, lB1, 2);
    const float invA0 = 1.0f / lA0;
    const float invA1 = 1.0f / lA1;
    const float invB0 = 1.0f / lB0;
    const float invB1 = 1.0f / lB1;

    // ---- normalize + write O ----
    float* oA0 = out + (size_t)(plane + qgA) * Dd;
    float* oA1 = oA0 + 8 * Dd;
    float* oB0 = out + (size_t)(plane + qgB) * Dd;
    float* oB1 = oB0 + 8 * Dd;
#pragma unroll
    for (int n0 = 0; n0 < 8; n0++) {
        *(float2*)&oA0[n0 * 8 + 2 * tig] =
            make_float2(oaccA[n0][0] * invA0, oaccA[n0][1] * invA0);
        *(float2*)&oA1[n0 * 8 + 2 * tig] =
            make_float2(oaccA[n0][2] * invA1, oaccA[n0][3] * invA1);
        *(float2*)&oB0[n0 * 8 + 2 * tig] =
            make_float2(oaccB[n0][0] * invB0, oaccB[n0][1] * invB0);
        *(float2*)&oB1[n0 * 8 + 2 * tig] =
            make_float2(oaccB[n0][2] * invB1, oaccB[n0][3] * invB1);
    }
}

// ---------------------------------------------------------------------------
extern "C" void kernel_launch(void* const* d_in, const int* in_sizes, int n_in,
                              void* d_out, int out_size) {
    const float* q    = (const float*)d_in[0];
    const float* k    = (const float*)d_in[1];
    const float* v    = (const float*)d_in[2];
    const void*  mask = d_in[3];
    const float* taus = (const float*)d_in[4];
    const float* bias = (const float*)d_in[5];
    float*       out  = (float*)d_out;
    (void)in_sizes; (void)n_in; (void)out_size;

    const int smem_bytes = SMEM_WORDS * 4;
    cudaFuncSetAttribute(attn_kernel, cudaFuncAttributeMaxDynamicSharedMemorySize,
                         smem_bytes);

    mask_prep_kernel<<<1, 1024>>>(mask);

    dim3 grid(Ss / BM, Hh, Bb);
    attn_kernel<<<grid, NTHREADS, smem_bytes>>>(q, k, v, taus, bias, out);
}